// round 1
// baseline (speedup 1.0000x reference)
#include <cuda_runtime.h>
#include <cuda_bf16.h>
#include <math.h>

#define NNODES 200000
#define NB     1024
#define NH     256
#define NH4    64      // NH/4
#define G3H    768
#define NOUT   128

// ---------------- scratch (device globals; no allocation allowed) ----------------
__device__ int   g_seg[NB + 1];
__device__ float g_wsrc[NH];
__device__ float g_wdst[NH];
__device__ float g_asrc[NNODES];
__device__ float g_adst[NB];
__device__ float g_out[NB * NH];
__device__ float g_s[NB * NH];
__device__ float g_h[NB * NH];
__device__ float g_gi[NB * G3H];
__device__ float g_gh[NB * G3H];

// ---------------- helpers ----------------
__device__ __forceinline__ float warp_sum(float v) {
#pragma unroll
    for (int off = 16; off; off >>= 1) v += __shfl_xor_sync(0xffffffffu, v, off);
    return v;
}
__device__ __forceinline__ float warp_max(float v) {
#pragma unroll
    for (int off = 16; off; off >>= 1) v = fmaxf(v, __shfl_xor_sync(0xffffffffu, v, off));
    return v;
}
__device__ __forceinline__ float sigmoidf_(float x) { return 1.0f / (1.0f + expf(-x)); }

// ---------------- segment offsets: lower_bound(batch, b) ----------------
__global__ void seg_kernel(const int* __restrict__ batch, int n) {
    int b = blockIdx.x * blockDim.x + threadIdx.x;
    if (b > NB) return;
    int lo = 0, hi = n;
    while (lo < hi) {
        int mid = (lo + hi) >> 1;
        if (batch[mid] < b) lo = mid + 1; else hi = mid;
    }
    g_seg[b] = lo;
}

// ---------------- w_att_src = W @ att_src ; w_att_dst = W @ att_dst --------------
// warp per output row (512 rows total: 0..255 src, 256..511 dst)
__global__ void watt_kernel(const float* __restrict__ W,
                            const float* __restrict__ att_src,
                            const float* __restrict__ att_dst) {
    int g = (blockIdx.x * blockDim.x + threadIdx.x) >> 5;
    int l = threadIdx.x & 31;
    if (g >= 2 * NH) return;
    int row = g & (NH - 1);
    bool isdst = g >= NH;
    const float4* Wr = reinterpret_cast<const float4*>(W + (size_t)row * NH);
    const float4* av = reinterpret_cast<const float4*>(isdst ? att_dst : att_src);
    float4 v0 = Wr[l], v1 = Wr[32 + l];
    float4 a0 = av[l], a1 = av[32 + l];
    float p = v0.x * a0.x + v0.y * a0.y + v0.z * a0.z + v0.w * a0.w +
              v1.x * a1.x + v1.y * a1.y + v1.z * a1.z + v1.w * a1.w;
    p = warp_sum(p);
    if (l == 0) (isdst ? g_wdst : g_wsrc)[row] = p;
}

// ---------------- phase A: out0[b] = sum_i x_i ; a_src[i] = x_i . w_att_src -------
// one block (256 threads = 8 warps) per graph; warp-per-node
__global__ void phaseA_kernel(const float4* __restrict__ x4) {
    int b = blockIdx.x;
    int lo = g_seg[b], hi = g_seg[b + 1];
    int tid = threadIdx.x, w = tid >> 5, l = tid & 31;
    __shared__ float red[8][NH];

    const float4* wa = reinterpret_cast<const float4*>(g_wsrc);
    float4 w0 = wa[l], w1 = wa[32 + l];
    float4 a0 = make_float4(0.f, 0.f, 0.f, 0.f);
    float4 a1 = make_float4(0.f, 0.f, 0.f, 0.f);

    for (int i = lo + w; i < hi; i += 8) {
        const float4* row = x4 + (size_t)i * NH4;
        float4 v0 = row[l], v1 = row[32 + l];
        a0.x += v0.x; a0.y += v0.y; a0.z += v0.z; a0.w += v0.w;
        a1.x += v1.x; a1.y += v1.y; a1.z += v1.z; a1.w += v1.w;
        float p = v0.x * w0.x + v0.y * w0.y + v0.z * w0.z + v0.w * w0.w +
                  v1.x * w1.x + v1.y * w1.y + v1.z * w1.z + v1.w * w1.w;
        p = warp_sum(p);
        if (l == 0) g_asrc[i] = p;
    }
    reinterpret_cast<float4*>(red[w])[l]      = a0;
    reinterpret_cast<float4*>(red[w])[32 + l] = a1;
    __syncthreads();
    float s = 0.f;
#pragma unroll
    for (int ww = 0; ww < 8; ww++) s += red[ww][tid];
    g_out[(size_t)b * NH + tid] = s;
}

// ---------------- a_dst[b] = out[b] . w_att_dst (warp per graph) ----------------
__global__ void adst_kernel() {
    int g = (blockIdx.x * blockDim.x + threadIdx.x) >> 5;
    int l = threadIdx.x & 31;
    if (g >= NB) return;
    const float4* row = reinterpret_cast<const float4*>(g_out) + (size_t)g * NH4;
    const float4* wa  = reinterpret_cast<const float4*>(g_wdst);
    float4 v0 = row[l], v1 = row[32 + l];
    float4 w0 = wa[l],  w1 = wa[32 + l];
    float p = v0.x * w0.x + v0.y * w0.y + v0.z * w0.z + v0.w * w0.w +
              v1.x * w1.x + v1.y * w1.y + v1.z * w1.z + v1.w * w1.w;
    p = warp_sum(p);
    if (l == 0) g_adst[g] = p;
}

// ---------------- softmax stats + weighted pool: s[b] = sum_i alpha_i x_i --------
__global__ void attnpool_kernel(const float4* __restrict__ x4) {
    int b = blockIdx.x;
    int lo = g_seg[b], hi = g_seg[b + 1];
    int tid = threadIdx.x, w = tid >> 5, l = tid & 31;
    __shared__ float red[8][NH];
    __shared__ float s_emax, s_denom;

    if (lo >= hi) {                       // empty graph: weighted sum = 0
        g_s[(size_t)b * NH + tid] = 0.f;
        return;
    }
    float adst = g_adst[b];

    // pass 1: max over leaky-relu'd scores
    float lmax = -INFINITY;
    for (int i = lo + tid; i < hi; i += 256) {
        float e = g_asrc[i] + adst;
        e = e > 0.f ? e : 0.01f * e;
        lmax = fmaxf(lmax, e);
    }
    lmax = warp_max(lmax);
    if (l == 0) red[0][w] = lmax;
    __syncthreads();
    if (tid == 0) {
        float m = red[0][0];
#pragma unroll
        for (int i = 1; i < 8; i++) m = fmaxf(m, red[0][i]);
        s_emax = m;
    }
    __syncthreads();
    float emax = s_emax;

    // pass 2: denom
    float lsum = 0.f;
    for (int i = lo + tid; i < hi; i += 256) {
        float e = g_asrc[i] + adst;
        e = e > 0.f ? e : 0.01f * e;
        lsum += expf(e - emax);
    }
    lsum = warp_sum(lsum);
    __syncthreads();
    if (l == 0) red[0][w] = lsum;
    __syncthreads();
    if (tid == 0) {
        float d = 0.f;
#pragma unroll
        for (int i = 0; i < 8; i++) d += red[0][i];
        s_denom = d;
    }
    __syncthreads();
    float invd = 1.0f / s_denom;

    // pass 3: warp-per-node weighted accumulation
    float4 a0 = make_float4(0.f, 0.f, 0.f, 0.f);
    float4 a1 = make_float4(0.f, 0.f, 0.f, 0.f);
    for (int i = lo + w; i < hi; i += 8) {
        float e = g_asrc[i] + adst;
        e = e > 0.f ? e : 0.01f * e;
        float alpha = expf(e - emax) * invd;
        const float4* row = x4 + (size_t)i * NH4;
        float4 v0 = row[l], v1 = row[32 + l];
        a0.x += alpha * v0.x; a0.y += alpha * v0.y; a0.z += alpha * v0.z; a0.w += alpha * v0.w;
        a1.x += alpha * v1.x; a1.y += alpha * v1.y; a1.z += alpha * v1.z; a1.w += alpha * v1.w;
    }
    __syncthreads();
    reinterpret_cast<float4*>(red[w])[l]      = a0;
    reinterpret_cast<float4*>(red[w])[32 + l] = a1;
    __syncthreads();
    float s = 0.f;
#pragma unroll
    for (int ww = 0; ww < 8; ww++) s += red[ww][tid];
    g_s[(size_t)b * NH + tid] = s;
}

// ---------------- tiled GEMM: C[M,Nc] = A[M,K] @ op(B) + bias, optional ELU ------
// TRANS_B=0: B is [K,Nc] row-major.  TRANS_B=1: B is [Nc,K] row-major (C=A@B^T).
// ACT: 0 none, 1 ELU.
template <int TRANS_B, int ACT>
__global__ void gemm_kernel(const float* __restrict__ A, const float* __restrict__ Bm,
                            const float* __restrict__ bias, float* __restrict__ C,
                            int M, int Nc, int K) {
    __shared__ float As[16][64];
    __shared__ float Bs[16][65];
    int bm = blockIdx.x * 64, bn = blockIdx.y * 64;
    int tid = threadIdx.x;
    int ty = tid >> 4, tx = tid & 15;
    float acc[4][4];
#pragma unroll
    for (int i = 0; i < 4; i++)
#pragma unroll
        for (int j = 0; j < 4; j++) acc[i][j] = 0.f;

    for (int k0 = 0; k0 < K; k0 += 16) {
#pragma unroll
        for (int r = 0; r < 4; r++) {
            int idx = tid + r * 256;
            int m = idx >> 4, k = idx & 15;
            As[k][m] = A[(size_t)(bm + m) * K + k0 + k];
        }
#pragma unroll
        for (int r = 0; r < 4; r++) {
            int idx = tid + r * 256;
            if (TRANS_B) {
                int n = idx >> 4, k = idx & 15;
                Bs[k][n] = Bm[(size_t)(bn + n) * K + k0 + k];
            } else {
                int k = idx >> 6, n = idx & 63;
                Bs[k][n] = Bm[(size_t)(k0 + k) * Nc + bn + n];
            }
        }
        __syncthreads();
#pragma unroll
        for (int k = 0; k < 16; k++) {
            float a[4], bb[4];
#pragma unroll
            for (int i = 0; i < 4; i++) { a[i] = As[k][ty * 4 + i]; bb[i] = Bs[k][tx * 4 + i]; }
#pragma unroll
            for (int i = 0; i < 4; i++)
#pragma unroll
                for (int j = 0; j < 4; j++) acc[i][j] += a[i] * bb[j];
        }
        __syncthreads();
    }
#pragma unroll
    for (int i = 0; i < 4; i++)
#pragma unroll
        for (int j = 0; j < 4; j++) {
            int m = bm + ty * 4 + i, n = bn + tx * 4 + j;
            float v = acc[i][j] + bias[n];
            if (ACT == 1) v = v > 0.f ? v : expm1f(v);
            C[(size_t)m * Nc + n] = v;
        }
}

// ---------------- GRU elementwise update (in place on g_out) ----------------
__global__ void gru_kernel() {
    int idx = blockIdx.x * blockDim.x + threadIdx.x;
    if (idx >= NB * NH) return;
    int b = idx >> 8, h = idx & (NH - 1);
    const float* gib = g_gi + (size_t)b * G3H;
    const float* ghb = g_gh + (size_t)b * G3H;
    float r = sigmoidf_(gib[h] + ghb[h]);
    float z = sigmoidf_(gib[NH + h] + ghb[NH + h]);
    float n = tanhf(gib[2 * NH + h] + r * ghb[2 * NH + h]);
    float o = g_out[idx];
    float v = (1.0f - z) * n + z * o;
    g_out[idx] = v * sigmoidf_(v);     // silu
}

// ---------------- launch ----------------
extern "C" void kernel_launch(void* const* d_in, const int* in_sizes, int n_in,
                              void* d_out, int out_size) {
    const float* x        = (const float*)d_in[0];
    const int*   batch    = (const int*)d_in[1];
    const float* W        = (const float*)d_in[2];
    const float* att_src  = (const float*)d_in[3];
    const float* att_dst  = (const float*)d_in[4];
    const float* bias_gat = (const float*)d_in[5];
    const float* W_ih     = (const float*)d_in[6];
    const float* W_hh     = (const float*)d_in[7];
    const float* b_ih     = (const float*)d_in[8];
    const float* b_hh     = (const float*)d_in[9];
    const float* W_lin    = (const float*)d_in[10];
    const float* b_lin    = (const float*)d_in[11];
    float*       out      = (float*)d_out;

    const int n = in_sizes[1];   // number of nodes (200000)
    const float4* x4 = reinterpret_cast<const float4*>(x);

    // scratch addresses
    float *p_out, *p_s, *p_h, *p_gi, *p_gh;
    cudaGetSymbolAddress((void**)&p_out, g_out);
    cudaGetSymbolAddress((void**)&p_s,   g_s);
    cudaGetSymbolAddress((void**)&p_h,   g_h);
    cudaGetSymbolAddress((void**)&p_gi,  g_gi);
    cudaGetSymbolAddress((void**)&p_gh,  g_gh);

    seg_kernel<<<(NB + 1 + 255) / 256, 256>>>(batch, n);
    watt_kernel<<<(2 * NH * 32 + 255) / 256, 256>>>(W, att_src, att_dst);
    phaseA_kernel<<<NB, 256>>>(x4);

    for (int t = 0; t < 2; t++) {
        adst_kernel<<<NB * 32 / 256, 256>>>();
        attnpool_kernel<<<NB, 256>>>(x4);
        // h = elu(s @ W + bias_gat)
        {
            dim3 grid(NB / 64, NH / 64);
            gemm_kernel<0, 1><<<grid, 256>>>(p_s, W, bias_gat, p_h, NB, NH, NH);
        }
        // gi = h @ W_ih^T + b_ih ; gh = out @ W_hh^T + b_hh
        {
            dim3 grid(NB / 64, G3H / 64);
            gemm_kernel<1, 0><<<grid, 256>>>(p_h,   W_ih, b_ih, p_gi, NB, G3H, NH);
            gemm_kernel<1, 0><<<grid, 256>>>(p_out, W_hh, b_hh, p_gh, NB, G3H, NH);
        }
        gru_kernel<<<NB * NH / 256, 256>>>();
    }

    // final: out @ W_lin + b_lin -> d_out [NB, NOUT]
    {
        dim3 grid(NB / 64, NOUT / 64);
        gemm_kernel<0, 0><<<grid, 256>>>(p_out, W_lin, b_lin, out, NB, NOUT, NH);
    }
}

// round 2
// speedup vs baseline: 1.1174x; 1.1174x over previous
#include <cuda_runtime.h>
#include <cuda_bf16.h>
#include <math.h>

#define NNODES 200000
#define NB     1024
#define NH     256
#define NH4    64      // NH/4
#define G3H    768
#define NOUT   128

// ---------------- scratch (device globals; no allocation allowed) ----------------
__device__ int   g_seg[NB + 1];
__device__ float g_wsrc[NH];
__device__ float g_wdst[NH];
__device__ float g_asrc[NNODES];
__device__ float g_out[NB * NH];
__device__ float g_s[NB * NH];
__device__ float g_h[NB * NH];
__device__ float g_gi[NB * G3H];
__device__ float g_gh[NB * G3H];

// ---------------- helpers ----------------
__device__ __forceinline__ float warp_sum(float v) {
#pragma unroll
    for (int off = 16; off; off >>= 1) v += __shfl_xor_sync(0xffffffffu, v, off);
    return v;
}
__device__ __forceinline__ float sigmoidf_(float x) { return 1.0f / (1.0f + expf(-x)); }
__device__ __forceinline__ float dot4(float4 a, float4 b) {
    return a.x * b.x + a.y * b.y + a.z * b.z + a.w * b.w;
}

// ---------------- segment offsets: lower_bound(batch, b) ----------------
__global__ void seg_kernel(const int* __restrict__ batch, int n) {
    int b = blockIdx.x * blockDim.x + threadIdx.x;
    if (b > NB) return;
    int lo = 0, hi = n;
    while (lo < hi) {
        int mid = (lo + hi) >> 1;
        if (batch[mid] < b) lo = mid + 1; else hi = mid;
    }
    g_seg[b] = lo;
}

// ---------------- w_att_src = W @ att_src ; w_att_dst = W @ att_dst --------------
__global__ void watt_kernel(const float* __restrict__ W,
                            const float* __restrict__ att_src,
                            const float* __restrict__ att_dst) {
    int g = (blockIdx.x * blockDim.x + threadIdx.x) >> 5;
    int l = threadIdx.x & 31;
    if (g >= 2 * NH) return;
    int row = g & (NH - 1);
    bool isdst = g >= NH;
    const float4* Wr = reinterpret_cast<const float4*>(W + (size_t)row * NH);
    const float4* av = reinterpret_cast<const float4*>(isdst ? att_dst : att_src);
    float p = dot4(Wr[l], av[l]) + dot4(Wr[32 + l], av[32 + l]);
    p = warp_sum(p);
    if (l == 0) (isdst ? g_wdst : g_wsrc)[row] = p;
}

// ---------------- phase A: out0[b] = sum_i x_i ; a_src[i] = x_i . w_att_src -------
__global__ void phaseA_kernel(const float4* __restrict__ x4) {
    int b = blockIdx.x;
    int lo = g_seg[b], hi = g_seg[b + 1];
    int tid = threadIdx.x, w = tid >> 5, l = tid & 31;
    __shared__ float red[8][NH];

    const float4* wa = reinterpret_cast<const float4*>(g_wsrc);
    float4 w0 = wa[l], w1 = wa[32 + l];
    float4 a0 = make_float4(0.f, 0.f, 0.f, 0.f);
    float4 a1 = make_float4(0.f, 0.f, 0.f, 0.f);

    int i = lo + w;
    for (; i + 8 < hi; i += 16) {
        const float4* r0 = x4 + (size_t)i * NH4;
        const float4* r1 = x4 + (size_t)(i + 8) * NH4;
        float4 u0 = r0[l], u1 = r0[32 + l];
        float4 v0 = r1[l], v1 = r1[32 + l];
        a0.x += u0.x + v0.x; a0.y += u0.y + v0.y; a0.z += u0.z + v0.z; a0.w += u0.w + v0.w;
        a1.x += u1.x + v1.x; a1.y += u1.y + v1.y; a1.z += u1.z + v1.z; a1.w += u1.w + v1.w;
        float p = dot4(u0, w0) + dot4(u1, w1);
        float q = dot4(v0, w0) + dot4(v1, w1);
        p = warp_sum(p);
        q = warp_sum(q);
        if (l == 0) { g_asrc[i] = p; g_asrc[i + 8] = q; }
    }
    if (i < hi) {
        const float4* r0 = x4 + (size_t)i * NH4;
        float4 u0 = r0[l], u1 = r0[32 + l];
        a0.x += u0.x; a0.y += u0.y; a0.z += u0.z; a0.w += u0.w;
        a1.x += u1.x; a1.y += u1.y; a1.z += u1.z; a1.w += u1.w;
        float p = dot4(u0, w0) + dot4(u1, w1);
        p = warp_sum(p);
        if (l == 0) g_asrc[i] = p;
    }
    reinterpret_cast<float4*>(red[w])[l]      = a0;
    reinterpret_cast<float4*>(red[w])[32 + l] = a1;
    __syncthreads();
    float s = 0.f;
#pragma unroll
    for (int ww = 0; ww < 8; ww++) s += red[ww][tid];
    g_out[(size_t)b * NH + tid] = s;
}

// ---------------- fused: a_dst + single-pass weighted pool (no emax; exact) -------
__global__ void attnpool_kernel(const float4* __restrict__ x4) {
    int b = blockIdx.x;
    int lo = g_seg[b], hi = g_seg[b + 1];
    int tid = threadIdx.x, w = tid >> 5, l = tid & 31;
    __shared__ float red[8][NH];
    __shared__ float sred[8];
    __shared__ float s_adst, s_invd;

    if (lo >= hi) {
        g_s[(size_t)b * NH + tid] = 0.f;
        return;
    }

    // a_dst = out[b] . w_att_dst (256-thread reduce)
    float p = g_out[(size_t)b * NH + tid] * g_wdst[tid];
    p = warp_sum(p);
    if (l == 0) sred[w] = p;
    __syncthreads();
    if (tid == 0) {
        float s = 0.f;
#pragma unroll
        for (int i = 0; i < 8; i++) s += sred[i];
        s_adst = s;
    }
    __syncthreads();
    float adst = s_adst;

    // single pass: acc = sum_i w_i * x_i ; dsum = sum_i w_i, w = exp(leakyrelu(e))
    float4 a0 = make_float4(0.f, 0.f, 0.f, 0.f);
    float4 a1 = make_float4(0.f, 0.f, 0.f, 0.f);
    float dsum = 0.f;

    int i = lo + w;
    for (; i + 8 < hi; i += 16) {
        float e0 = g_asrc[i] + adst;     e0 = e0 > 0.f ? e0 : 0.01f * e0;
        float e1 = g_asrc[i + 8] + adst; e1 = e1 > 0.f ? e1 : 0.01f * e1;
        float al0 = __expf(e0), al1 = __expf(e1);
        dsum += al0 + al1;
        const float4* r0 = x4 + (size_t)i * NH4;
        const float4* r1 = x4 + (size_t)(i + 8) * NH4;
        float4 u0 = r0[l], u1 = r0[32 + l];
        float4 v0 = r1[l], v1 = r1[32 + l];
        a0.x += al0 * u0.x + al1 * v0.x; a0.y += al0 * u0.y + al1 * v0.y;
        a0.z += al0 * u0.z + al1 * v0.z; a0.w += al0 * u0.w + al1 * v0.w;
        a1.x += al0 * u1.x + al1 * v1.x; a1.y += al0 * u1.y + al1 * v1.y;
        a1.z += al0 * u1.z + al1 * v1.z; a1.w += al0 * u1.w + al1 * v1.w;
    }
    if (i < hi) {
        float e0 = g_asrc[i] + adst; e0 = e0 > 0.f ? e0 : 0.01f * e0;
        float al0 = __expf(e0);
        dsum += al0;
        const float4* r0 = x4 + (size_t)i * NH4;
        float4 u0 = r0[l], u1 = r0[32 + l];
        a0.x += al0 * u0.x; a0.y += al0 * u0.y; a0.z += al0 * u0.z; a0.w += al0 * u0.w;
        a1.x += al0 * u1.x; a1.y += al0 * u1.y; a1.z += al0 * u1.z; a1.w += al0 * u1.w;
    }
    // per-warp dsum: all lanes hold the same value (uniform per row)
    __syncthreads();
    if (l == 0) sred[w] = dsum;
    reinterpret_cast<float4*>(red[w])[l]      = a0;
    reinterpret_cast<float4*>(red[w])[32 + l] = a1;
    __syncthreads();
    if (tid == 0) {
        float d = 0.f;
#pragma unroll
        for (int i2 = 0; i2 < 8; i2++) d += sred[i2];
        s_invd = 1.0f / d;
    }
    __syncthreads();
    float invd = s_invd;
    float s = 0.f;
#pragma unroll
    for (int ww = 0; ww < 8; ww++) s += red[ww][tid];
    g_s[(size_t)b * NH + tid] = s * invd;
}

// ---------------- GEMM: 64x64 tile, 128 threads, 8x4 micro-tile ----------------
// TRANS_B=0: B is [K,N] row-major.  TRANS_B=1: B is [N,K] row-major (C = A@B^T).
// ACT: 0 none, 1 ELU.
template <int TRANS_B, int ACT>
__device__ __forceinline__ void gemm_body(const float* __restrict__ A, const float* __restrict__ B,
                                          const float* __restrict__ bias, float* __restrict__ C,
                                          int M, int N, int K, int bm, int bn) {
    __shared__ float As[16][64];
    __shared__ float Bs[16][64];
    int tid = threadIdx.x;
    int ty = tid >> 4, tx = tid & 15;    // ty 0..7 (8 rows each), tx 0..15 (4 cols each)
    float acc[8][4];
#pragma unroll
    for (int i = 0; i < 8; i++)
#pragma unroll
        for (int j = 0; j < 4; j++) acc[i][j] = 0.f;

    for (int k0 = 0; k0 < K; k0 += 16) {
#pragma unroll
        for (int r = 0; r < 2; r++) {
            int e = tid + r * 128;
            int m = e >> 2, kq = e & 3;
            float4 v = *reinterpret_cast<const float4*>(&A[(size_t)(bm + m) * K + k0 + kq * 4]);
            As[kq * 4 + 0][m] = v.x; As[kq * 4 + 1][m] = v.y;
            As[kq * 4 + 2][m] = v.z; As[kq * 4 + 3][m] = v.w;
        }
#pragma unroll
        for (int r = 0; r < 2; r++) {
            int e = tid + r * 128;
            if (TRANS_B) {
                int n = e >> 2, kq = e & 3;
                float4 v = *reinterpret_cast<const float4*>(&B[(size_t)(bn + n) * K + k0 + kq * 4]);
                Bs[kq * 4 + 0][n] = v.x; Bs[kq * 4 + 1][n] = v.y;
                Bs[kq * 4 + 2][n] = v.z; Bs[kq * 4 + 3][n] = v.w;
            } else {
                int k = e >> 4, nq = e & 15;
                float4 v = *reinterpret_cast<const float4*>(&B[(size_t)(k0 + k) * N + bn + nq * 4]);
                *reinterpret_cast<float4*>(&Bs[k][nq * 4]) = v;
            }
        }
        __syncthreads();
#pragma unroll
        for (int k = 0; k < 16; k++) {
            float4 a0 = *reinterpret_cast<float4*>(&As[k][ty * 8]);
            float4 a1 = *reinterpret_cast<float4*>(&As[k][ty * 8 + 4]);
            float4 bv = *reinterpret_cast<float4*>(&Bs[k][tx * 4]);
            float a[8] = {a0.x, a0.y, a0.z, a0.w, a1.x, a1.y, a1.z, a1.w};
            float bb[4] = {bv.x, bv.y, bv.z, bv.w};
#pragma unroll
            for (int i = 0; i < 8; i++)
#pragma unroll
                for (int j = 0; j < 4; j++) acc[i][j] += a[i] * bb[j];
        }
        __syncthreads();
    }
    float4 bvec = *reinterpret_cast<const float4*>(&bias[bn + tx * 4]);
    float bb[4] = {bvec.x, bvec.y, bvec.z, bvec.w};
#pragma unroll
    for (int i = 0; i < 8; i++) {
        float4 o;
        o.x = acc[i][0] + bb[0];
        o.y = acc[i][1] + bb[1];
        o.z = acc[i][2] + bb[2];
        o.w = acc[i][3] + bb[3];
        if (ACT == 1) {
            o.x = o.x > 0.f ? o.x : expm1f(o.x);
            o.y = o.y > 0.f ? o.y : expm1f(o.y);
            o.z = o.z > 0.f ? o.z : expm1f(o.z);
            o.w = o.w > 0.f ? o.w : expm1f(o.w);
        }
        *reinterpret_cast<float4*>(&C[(size_t)(bm + ty * 8 + i) * N + bn + tx * 4]) = o;
    }
}

template <int TRANS_B, int ACT>
__global__ void gemm_kernel(const float* __restrict__ A, const float* __restrict__ B,
                            const float* __restrict__ bias, float* __restrict__ C,
                            int M, int N, int K) {
    gemm_body<TRANS_B, ACT>(A, B, bias, C, M, N, K, blockIdx.x * 64, blockIdx.y * 64);
}

// gi = h @ W_ih^T + b_ih (z=0) ; gh = out @ W_hh^T + b_hh (z=1), one launch
__global__ void gemm_dual_kernel(const float* __restrict__ A0, const float* __restrict__ B0,
                                 const float* __restrict__ bias0, float* __restrict__ C0,
                                 const float* __restrict__ A1, const float* __restrict__ B1,
                                 const float* __restrict__ bias1, float* __restrict__ C1,
                                 int M, int N, int K) {
    if (blockIdx.z == 0)
        gemm_body<1, 0>(A0, B0, bias0, C0, M, N, K, blockIdx.x * 64, blockIdx.y * 64);
    else
        gemm_body<1, 0>(A1, B1, bias1, C1, M, N, K, blockIdx.x * 64, blockIdx.y * 64);
}

// ---------------- GRU elementwise update (float4, in place on g_out) ----------------
__global__ void gru_kernel() {
    int idx = blockIdx.x * blockDim.x + threadIdx.x;   // NB * NH4 threads
    if (idx >= NB * NH4) return;
    int b = idx >> 6, h4 = idx & 63;
    const float4* gi4 = reinterpret_cast<const float4*>(g_gi) + (size_t)b * (G3H / 4);
    const float4* gh4 = reinterpret_cast<const float4*>(g_gh) + (size_t)b * (G3H / 4);
    float4 gir = gi4[h4], giz = gi4[64 + h4], gin = gi4[128 + h4];
    float4 ghr = gh4[h4], ghz = gh4[64 + h4], ghn = gh4[128 + h4];
    float4* out4 = reinterpret_cast<float4*>(g_out) + idx;
    float4 o = *out4;
    float4 res;
    {
        float r = sigmoidf_(gir.x + ghr.x);
        float z = sigmoidf_(giz.x + ghz.x);
        float n = tanhf(gin.x + r * ghn.x);
        float v = (1.0f - z) * n + z * o.x;
        res.x = v * sigmoidf_(v);
    }
    {
        float r = sigmoidf_(gir.y + ghr.y);
        float z = sigmoidf_(giz.y + ghz.y);
        float n = tanhf(gin.y + r * ghn.y);
        float v = (1.0f - z) * n + z * o.y;
        res.y = v * sigmoidf_(v);
    }
    {
        float r = sigmoidf_(gir.z + ghr.z);
        float z = sigmoidf_(giz.z + ghz.z);
        float n = tanhf(gin.z + r * ghn.z);
        float v = (1.0f - z) * n + z * o.z;
        res.z = v * sigmoidf_(v);
    }
    {
        float r = sigmoidf_(gir.w + ghr.w);
        float z = sigmoidf_(giz.w + ghz.w);
        float n = tanhf(gin.w + r * ghn.w);
        float v = (1.0f - z) * n + z * o.w;
        res.w = v * sigmoidf_(v);
    }
    *out4 = res;
}

// ---------------- launch ----------------
extern "C" void kernel_launch(void* const* d_in, const int* in_sizes, int n_in,
                              void* d_out, int out_size) {
    const float* x        = (const float*)d_in[0];
    const int*   batch    = (const int*)d_in[1];
    const float* W        = (const float*)d_in[2];
    const float* att_src  = (const float*)d_in[3];
    const float* att_dst  = (const float*)d_in[4];
    const float* bias_gat = (const float*)d_in[5];
    const float* W_ih     = (const float*)d_in[6];
    const float* W_hh     = (const float*)d_in[7];
    const float* b_ih     = (const float*)d_in[8];
    const float* b_hh     = (const float*)d_in[9];
    const float* W_lin    = (const float*)d_in[10];
    const float* b_lin    = (const float*)d_in[11];
    float*       out      = (float*)d_out;

    const int n = in_sizes[1];
    const float4* x4 = reinterpret_cast<const float4*>(x);

    float *p_out, *p_s, *p_h, *p_gi, *p_gh;
    cudaGetSymbolAddress((void**)&p_out, g_out);
    cudaGetSymbolAddress((void**)&p_s,   g_s);
    cudaGetSymbolAddress((void**)&p_h,   g_h);
    cudaGetSymbolAddress((void**)&p_gi,  g_gi);
    cudaGetSymbolAddress((void**)&p_gh,  g_gh);

    seg_kernel<<<(NB + 1 + 255) / 256, 256>>>(batch, n);
    watt_kernel<<<(2 * NH * 32 + 255) / 256, 256>>>(W, att_src, att_dst);
    phaseA_kernel<<<NB, 256>>>(x4);

    for (int t = 0; t < 2; t++) {
        attnpool_kernel<<<NB, 256>>>(x4);
        // h = elu(s @ W + bias_gat)
        gemm_kernel<0, 1><<<dim3(NB / 64, NH / 64), 128>>>(p_s, W, bias_gat, p_h, NB, NH, NH);
        // gi = h @ W_ih^T + b_ih ; gh = out @ W_hh^T + b_hh  (one launch, z=2)
        gemm_dual_kernel<<<dim3(NB / 64, G3H / 64, 2), 128>>>(
            p_h, W_ih, b_ih, p_gi, p_out, W_hh, b_hh, p_gh, NB, G3H, NH);
        gru_kernel<<<NB * NH4 / 256, 256>>>();
    }

    // final: out @ W_lin + b_lin -> d_out [NB, NOUT]
    gemm_kernel<0, 0><<<dim3(NB / 64, NOUT / 64), 128>>>(p_out, W_lin, b_lin, out, NB, NOUT, NH);
}

// round 3
// speedup vs baseline: 1.3536x; 1.2113x over previous
#include <cuda_runtime.h>
#include <math.h>

#define NNODES 200000
#define NB     1024
#define NH     256
#define NH4    64
#define G3H    768
#define NOUT   128
#define CH     512      // nodes per pool chunk

// ---------------- scratch ----------------
__device__ __align__(16) float g_wsrc[NH];
__device__ __align__(16) float g_wdst[NH];
__device__ __align__(16) float g_asrc[NNODES];
__device__ __align__(16) float g_adst[NB];
__device__ __align__(16) float g_out[NB * NH];
__device__ __align__(16) float g_sacc[NB * NH + NB];   // last NB floats = dsum
__device__ __align__(16) float g_h[NB * NH];
__device__ __align__(16) float g_gi[NB * G3H];
__device__ __align__(16) float g_gh[NB * G3H];
__device__ __align__(16) float g_WT[NH * NH];
__device__ __align__(16) float g_WlinT[NOUT * NH];

// ---------------- helpers ----------------
__device__ __forceinline__ float warp_sum(float v) {
#pragma unroll
    for (int off = 16; off; off >>= 1) v += __shfl_xor_sync(0xffffffffu, v, off);
    return v;
}
__device__ __forceinline__ float sigmoidf_(float x) { return 1.0f / (1.0f + expf(-x)); }
__device__ __forceinline__ float dot4(float4 a, float4 b) {
    return a.x * b.x + a.y * b.y + a.z * b.z + a.w * b.w;
}
__device__ __forceinline__ unsigned to_tf32(float x) {
    unsigned r;
    asm("cvt.rna.tf32.f32 %0, %1;" : "=r"(r) : "f"(x));
    return r;
}
__device__ __forceinline__ void mma_tf32(float* c, const unsigned* a, const unsigned* b) {
    asm volatile(
        "mma.sync.aligned.m16n8k8.row.col.f32.tf32.tf32.f32 "
        "{%0,%1,%2,%3}, {%4,%5,%6,%7}, {%8,%9}, {%0,%1,%2,%3};"
        : "+f"(c[0]), "+f"(c[1]), "+f"(c[2]), "+f"(c[3])
        : "r"(a[0]), "r"(a[1]), "r"(a[2]), "r"(a[3]), "r"(b[0]), "r"(b[1]));
}

// ---------------- w_att_src = W @ att_src ; w_att_dst = W @ att_dst --------------
__global__ void watt_kernel(const float* __restrict__ W,
                            const float* __restrict__ att_src,
                            const float* __restrict__ att_dst) {
    int g = (blockIdx.x * blockDim.x + threadIdx.x) >> 5;
    int l = threadIdx.x & 31;
    if (g >= 2 * NH) return;
    int row = g & (NH - 1);
    bool isdst = g >= NH;
    const float4* Wr = reinterpret_cast<const float4*>(W + (size_t)row * NH);
    const float4* av = reinterpret_cast<const float4*>(isdst ? att_dst : att_src);
    float p = dot4(Wr[l], av[l]) + dot4(Wr[32 + l], av[32 + l]);
    p = warp_sum(p);
    if (l == 0) (isdst ? g_wdst : g_wsrc)[row] = p;
}

// ---------------- transpose W -> WT, W_lin -> WlinT ----------------
__global__ void transpose_kernel(const float* __restrict__ W, const float* __restrict__ Wlin) {
    __shared__ float tile[32][33];
    int z = blockIdx.z;
    const float* src = z ? Wlin : W;
    float* dst = z ? g_WlinT : g_WT;
    int C = z ? NOUT : NH;    // cols of src ; rows = NH always
    int bx = blockIdx.x * 32, by = blockIdx.y * 32;
    if (bx >= C) return;
    int tx = threadIdx.x, ty = threadIdx.y;   // 32 x 8
#pragma unroll
    for (int j = 0; j < 32; j += 8)
        tile[ty + j][tx] = src[(size_t)(by + ty + j) * C + bx + tx];
    __syncthreads();
#pragma unroll
    for (int j = 0; j < 32; j += 8)
        dst[(size_t)(bx + ty + j) * NH + by + tx] = tile[tx][ty + j];
}

// ---------------- flush helper: add 8 floats (cols l*4.., 128+l*4..) ----------------
__device__ __forceinline__ void flush8(float* dst, int l, float4 a0, float4 a1) {
    float* p = dst + l * 4;
    atomicAdd(p + 0, a0.x); atomicAdd(p + 1, a0.y);
    atomicAdd(p + 2, a0.z); atomicAdd(p + 3, a0.w);
    p += 128;
    atomicAdd(p + 0, a1.x); atomicAdd(p + 1, a1.y);
    atomicAdd(p + 2, a1.z); atomicAdd(p + 3, a1.w);
}

// ---------------- phase A (chunked): asrc[i] = x_i . wsrc ; out0[b] += x_i --------
__global__ void phaseA_kernel(const float4* __restrict__ x4, const int* __restrict__ batch, int n) {
    int base = blockIdx.x * CH;
    int tid = threadIdx.x, w = tid >> 5, l = tid & 31;
    __shared__ float sacc[16][NH];
    for (int i = tid; i < 16 * NH; i += 256) (&sacc[0][0])[i] = 0.f;
    __syncthreads();
    int fg = batch[base];
    int lo = base + w * 64;
    int hi = min(base + (w + 1) * 64, n);

    const float4* wa = reinterpret_cast<const float4*>(g_wsrc);
    float4 w0 = wa[l], w1 = wa[32 + l];
    float4 a0 = make_float4(0.f, 0.f, 0.f, 0.f);
    float4 a1 = make_float4(0.f, 0.f, 0.f, 0.f);
    int cur = (lo < hi) ? batch[lo] : -1;

    for (int i = lo; i < hi; i++) {
        int bb = batch[i];
        if (bb != cur) {
            int slot = cur - fg;
            flush8(slot < 16 ? &sacc[slot][0] : &g_out[(size_t)cur * NH], l, a0, a1);
            a0 = make_float4(0.f, 0.f, 0.f, 0.f);
            a1 = make_float4(0.f, 0.f, 0.f, 0.f);
            cur = bb;
        }
        const float4* row = x4 + (size_t)i * NH4;
        float4 u0 = row[l], u1 = row[32 + l];
        a0.x += u0.x; a0.y += u0.y; a0.z += u0.z; a0.w += u0.w;
        a1.x += u1.x; a1.y += u1.y; a1.z += u1.z; a1.w += u1.w;
        float p = dot4(u0, w0) + dot4(u1, w1);
        p = warp_sum(p);
        if (l == 0) g_asrc[i] = p;
    }
    if (cur >= 0) {
        int slot = cur - fg;
        flush8(slot < 16 ? &sacc[slot][0] : &g_out[(size_t)cur * NH], l, a0, a1);
    }
    __syncthreads();
    int last = min(base + CH, n) - 1;
    int nspan = min(batch[last] - fg + 1, 16);
    for (int s = 0; s < nspan; s++)
        atomicAdd(&g_out[(size_t)(fg + s) * NH + tid], sacc[s][tid]);
}

// ---------------- adst[b] = out[b] . wdst ----------------
__global__ void adst_kernel() {
    int b = blockIdx.x, tid = threadIdx.x, w = tid >> 5, l = tid & 31;
    __shared__ float sr[8];
    float p = g_out[(size_t)b * NH + tid] * g_wdst[tid];
    p = warp_sum(p);
    if (l == 0) sr[w] = p;
    __syncthreads();
    if (tid == 0) {
        float s = 0.f;
#pragma unroll
        for (int i = 0; i < 8; i++) s += sr[i];
        g_adst[b] = s;
    }
}

// ---------------- attention pool (chunked, unnormalized + dsum) ----------------
__global__ void attnpool_kernel(const float4* __restrict__ x4, const int* __restrict__ batch, int n) {
    int base = blockIdx.x * CH;
    int tid = threadIdx.x, w = tid >> 5, l = tid & 31;
    __shared__ float sacc[16][NH];
    __shared__ float sds[16];
    for (int i = tid; i < 16 * NH; i += 256) (&sacc[0][0])[i] = 0.f;
    if (tid < 16) sds[tid] = 0.f;
    __syncthreads();
    int fg = batch[base];
    int lo = base + w * 64;
    int hi = min(base + (w + 1) * 64, n);
    float* gdsum = g_sacc + (size_t)NB * NH;

    float4 a0 = make_float4(0.f, 0.f, 0.f, 0.f);
    float4 a1 = make_float4(0.f, 0.f, 0.f, 0.f);
    float dloc = 0.f;
    int cur = (lo < hi) ? batch[lo] : -1;
    float adc = (cur >= 0) ? g_adst[cur] : 0.f;

    for (int i = lo; i < hi; i++) {
        int bb = batch[i];
        if (bb != cur) {
            int slot = cur - fg;
            flush8(slot < 16 ? &sacc[slot][0] : &g_sacc[(size_t)cur * NH], l, a0, a1);
            if (l == 0) {
                if (slot < 16) atomicAdd(&sds[slot], dloc);
                else atomicAdd(&gdsum[cur], dloc);
            }
            a0 = make_float4(0.f, 0.f, 0.f, 0.f);
            a1 = make_float4(0.f, 0.f, 0.f, 0.f);
            dloc = 0.f;
            cur = bb;
            adc = g_adst[bb];
        }
        float e = g_asrc[i] + adc;
        e = e > 0.f ? e : 0.01f * e;
        float wgt = __expf(e);
        dloc += wgt;
        const float4* row = x4 + (size_t)i * NH4;
        float4 u0 = row[l], u1 = row[32 + l];
        a0.x += wgt * u0.x; a0.y += wgt * u0.y; a0.z += wgt * u0.z; a0.w += wgt * u0.w;
        a1.x += wgt * u1.x; a1.y += wgt * u1.y; a1.z += wgt * u1.z; a1.w += wgt * u1.w;
    }
    if (cur >= 0) {
        int slot = cur - fg;
        flush8(slot < 16 ? &sacc[slot][0] : &g_sacc[(size_t)cur * NH], l, a0, a1);
        if (l == 0) {
            if (slot < 16) atomicAdd(&sds[slot], dloc);
            else atomicAdd(&gdsum[cur], dloc);
        }
    }
    __syncthreads();
    int last = min(base + CH, n) - 1;
    int nspan = min(batch[last] - fg + 1, 16);
    for (int s = 0; s < nspan; s++)
        atomicAdd(&g_sacc[(size_t)(fg + s) * NH + tid], sacc[s][tid]);
    if (tid < nspan) atomicAdd(&gdsum[fg + tid], sds[tid]);
}

// ---------------- tf32 tensor-core GEMM, NT: C = A[M,256] @ B[N,256]^T + bias ----
// ACT: 1 = ELU.  SCALE: 1 = multiply row by 1/dsum[row] (softmax normalization).
template <int ACT, int SCALE>
__device__ __forceinline__ void gemm_nt(unsigned (*As)[36], unsigned (*Bs)[36],
                                        const float* __restrict__ A, const float* __restrict__ B,
                                        const float* __restrict__ bias, float* __restrict__ C,
                                        int N, int bm, int bn) {
    const int K = 256;
    int tid = threadIdx.x;
    int lane = tid & 31, wp = tid >> 5;
    int wm = wp >> 1, wn = wp & 1;
    int g = lane >> 2, t = lane & 3;
    float acc[2][4][4];
#pragma unroll
    for (int i = 0; i < 2; i++)
#pragma unroll
        for (int j = 0; j < 4; j++)
#pragma unroll
            for (int r = 0; r < 4; r++) acc[i][j][r] = 0.f;

    for (int k0 = 0; k0 < K; k0 += 32) {
#pragma unroll
        for (int r = 0; r < 4; r++) {
            int e = tid + r * 128;
            int m = e >> 3, kq = e & 7;
            float4 va = *reinterpret_cast<const float4*>(&A[(size_t)(bm + m) * K + k0 + kq * 4]);
            As[m][kq * 4 + 0] = to_tf32(va.x);
            As[m][kq * 4 + 1] = to_tf32(va.y);
            As[m][kq * 4 + 2] = to_tf32(va.z);
            As[m][kq * 4 + 3] = to_tf32(va.w);
            float4 vb = *reinterpret_cast<const float4*>(&B[(size_t)(bn + m) * K + k0 + kq * 4]);
            Bs[m][kq * 4 + 0] = to_tf32(vb.x);
            Bs[m][kq * 4 + 1] = to_tf32(vb.y);
            Bs[m][kq * 4 + 2] = to_tf32(vb.z);
            Bs[m][kq * 4 + 3] = to_tf32(vb.w);
        }
        __syncthreads();
#pragma unroll
        for (int ks = 0; ks < 4; ks++) {
            int k8 = ks * 8;
            unsigned af[2][4], bf[4][2];
#pragma unroll
            for (int ti = 0; ti < 2; ti++) {
                int r0 = wm * 32 + ti * 16 + g;
                af[ti][0] = As[r0][k8 + t];
                af[ti][1] = As[r0 + 8][k8 + t];
                af[ti][2] = As[r0][k8 + t + 4];
                af[ti][3] = As[r0 + 8][k8 + t + 4];
            }
#pragma unroll
            for (int tj = 0; tj < 4; tj++) {
                int nr = wn * 32 + tj * 8 + g;
                bf[tj][0] = Bs[nr][k8 + t];
                bf[tj][1] = Bs[nr][k8 + t + 4];
            }
#pragma unroll
            for (int ti = 0; ti < 2; ti++)
#pragma unroll
                for (int tj = 0; tj < 4; tj++) mma_tf32(acc[ti][tj], af[ti], bf[tj]);
        }
        __syncthreads();
    }
    const float* dsum = g_sacc + (size_t)NB * NH;
#pragma unroll
    for (int ti = 0; ti < 2; ti++) {
        int r0 = bm + wm * 32 + ti * 16 + g;
        float invl = 1.f, invh = 1.f;
        if (SCALE) {
            float d0 = dsum[r0];
            float d1 = dsum[r0 + 8];
            invl = d0 > 0.f ? 1.f / d0 : 0.f;
            invh = d1 > 0.f ? 1.f / d1 : 0.f;
        }
#pragma unroll
        for (int tj = 0; tj < 4; tj++) {
            int col = bn + wn * 32 + tj * 8 + 2 * t;
            float b0 = bias[col], b1 = bias[col + 1];
            float c0 = acc[ti][tj][0] * invl + b0;
            float c1 = acc[ti][tj][1] * invl + b1;
            float c2 = acc[ti][tj][2] * invh + b0;
            float c3 = acc[ti][tj][3] * invh + b1;
            if (ACT) {
                c0 = c0 > 0.f ? c0 : expm1f(c0);
                c1 = c1 > 0.f ? c1 : expm1f(c1);
                c2 = c2 > 0.f ? c2 : expm1f(c2);
                c3 = c3 > 0.f ? c3 : expm1f(c3);
            }
            *reinterpret_cast<float2*>(&C[(size_t)r0 * N + col]) = make_float2(c0, c1);
            *reinterpret_cast<float2*>(&C[(size_t)(r0 + 8) * N + col]) = make_float2(c2, c3);
        }
    }
}

// h = elu((sacc/dsum) @ W + bias_gat)   [64 blocks]  +  gh = out @ W_hh^T + b_hh [192]
__global__ void gemm_h_gh_kernel(const float* __restrict__ W_hh,
                                 const float* __restrict__ bias_gat,
                                 const float* __restrict__ b_hh) {
    __shared__ unsigned As[64][36];
    __shared__ unsigned Bs[64][36];
    int bid = blockIdx.x;
    if (bid < 64)
        gemm_nt<1, 1>(As, Bs, g_sacc, g_WT, bias_gat, g_h, NH, (bid >> 2) * 64, (bid & 3) * 64);
    else {
        int b2 = bid - 64;
        gemm_nt<0, 0>(As, Bs, g_out, W_hh, b_hh, g_gh, G3H, (b2 / 12) * 64, (b2 % 12) * 64);
    }
}

__global__ void gemm_gi_kernel(const float* __restrict__ W_ih, const float* __restrict__ b_ih) {
    __shared__ unsigned As[64][36];
    __shared__ unsigned Bs[64][36];
    gemm_nt<0, 0>(As, Bs, g_h, W_ih, b_ih, g_gi, G3H,
                  (blockIdx.x / 12) * 64, (blockIdx.x % 12) * 64);
}

__global__ void gemm_final_kernel(const float* __restrict__ b_lin, float* __restrict__ out) {
    __shared__ unsigned As[64][36];
    __shared__ unsigned Bs[64][36];
    gemm_nt<0, 0>(As, Bs, g_out, g_WlinT, b_lin, out, NOUT,
                  (blockIdx.x >> 1) * 64, (blockIdx.x & 1) * 64);
}

// ---------------- GRU update (in place) + fused adst for next iteration ----------
__global__ void gru_adst_kernel() {
    int b = blockIdx.x, tid = threadIdx.x, w = tid >> 5, l = tid & 31;
    __shared__ float sr[8];
    const float* gib = g_gi + (size_t)b * G3H;
    const float* ghb = g_gh + (size_t)b * G3H;
    float r = sigmoidf_(gib[tid] + ghb[tid]);
    float z = sigmoidf_(gib[NH + tid] + ghb[NH + tid]);
    float nn = tanhf(gib[2 * NH + tid] + r * ghb[2 * NH + tid]);
    float o = g_out[(size_t)b * NH + tid];
    float v = (1.0f - z) * nn + z * o;
    v = v * sigmoidf_(v);
    g_out[(size_t)b * NH + tid] = v;
    float p = v * g_wdst[tid];
    p = warp_sum(p);
    if (l == 0) sr[w] = p;
    __syncthreads();
    if (tid == 0) {
        float s = 0.f;
#pragma unroll
        for (int i = 0; i < 8; i++) s += sr[i];
        g_adst[b] = s;
    }
}

// ---------------- launch ----------------
extern "C" void kernel_launch(void* const* d_in, const int* in_sizes, int n_in,
                              void* d_out, int out_size) {
    const float* x        = (const float*)d_in[0];
    const int*   batch    = (const int*)d_in[1];
    const float* W        = (const float*)d_in[2];
    const float* att_src  = (const float*)d_in[3];
    const float* att_dst  = (const float*)d_in[4];
    const float* bias_gat = (const float*)d_in[5];
    const float* W_ih     = (const float*)d_in[6];
    const float* W_hh     = (const float*)d_in[7];
    const float* b_ih     = (const float*)d_in[8];
    const float* b_hh     = (const float*)d_in[9];
    const float* W_lin    = (const float*)d_in[10];
    const float* b_lin    = (const float*)d_in[11];
    float*       out      = (float*)d_out;

    const int n = in_sizes[1];
    const int nch = (n + CH - 1) / CH;
    const float4* x4 = reinterpret_cast<const float4*>(x);

    float *p_out, *p_sacc;
    cudaGetSymbolAddress((void**)&p_out, g_out);
    cudaGetSymbolAddress((void**)&p_sacc, g_sacc);

    watt_kernel<<<64, 256>>>(W, att_src, att_dst);
    transpose_kernel<<<dim3(8, 8, 2), dim3(32, 8)>>>(W, W_lin);
    cudaMemsetAsync(p_out, 0, NB * NH * sizeof(float));
    phaseA_kernel<<<nch, 256>>>(x4, batch, n);
    adst_kernel<<<NB, 256>>>();

    for (int t = 0; t < 2; t++) {
        cudaMemsetAsync(p_sacc, 0, (NB * NH + NB) * sizeof(float));
        attnpool_kernel<<<nch, 256>>>(x4, batch, n);
        gemm_h_gh_kernel<<<256, 128>>>(W_hh, bias_gat, b_hh);
        gemm_gi_kernel<<<192, 128>>>(W_ih, b_ih);
        gru_adst_kernel<<<NB, 256>>>();
    }

    gemm_final_kernel<<<32, 128>>>(b_lin, out);
}